// round 15
// baseline (speedup 1.0000x reference)
#include <cuda_runtime.h>
#include <math.h>
#include <stdint.h>

// Problem-size maxima (fixed benchmark shape B=64, P=24564, C=81, T=50)
#define BMAX 64
#define PMAX 24564
#define TMAX 50
#define NSTRIPE 512

// ---------------- scratch (__device__ globals; no allocation allowed) -------
__device__ float               g_bt_ov [BMAX * PMAX];   // best truth overlap per prior
__device__ int                 g_bt_idx[BMAX * PMAX];   // best truth index per prior
__device__ float               g_mine  [BMAX * PMAX];   // fallback path only
__device__ float2              g_lsebg [BMAX * PMAX];   // {logsumexp, background logit}
__device__ unsigned long long  g_best_enc[BMAX * TMAX]; // per-gt best prior (encoded)
__device__ int                 g_num_pos[BMAX];
__device__ double              g_lossl_part[NSTRIPE];   // striped accumulators
__device__ double              g_lossc_part[NSTRIPE];

// ---------------- init ------------------------------------------------------
__global__ void k_init(int B, int T) {
    int i = blockIdx.x * blockDim.x + threadIdx.x;
    if (i < NSTRIPE) { g_lossl_part[i] = 0.0; g_lossc_part[i] = 0.0; }
    if (i < B) g_num_pos[i] = 0;
    if (i < B * T) g_best_enc[i] = 0ull;
}

// ---------------- fused matching + streaming logsumexp ----------------------
__device__ __forceinline__ void match_body(const float* __restrict__ priors,
                                           const float* __restrict__ tboxes,
                                           int P, int T, int b, int pblk) {
    __shared__ float4 s_t[TMAX];
    __shared__ float  s_ar[TMAX];
    __shared__ unsigned long long s_best[TMAX];
    int tid = threadIdx.x;
    if (tid < T) {
        const float* tb = tboxes + ((size_t)b * T + tid) * 4;
        float x1 = tb[0], y1 = tb[1], x2 = tb[2], y2 = tb[3];
        s_t[tid] = make_float4(x1, y1, x2, y2);
        s_ar[tid] = (x2 - x1) * (y2 - y1);
        s_best[tid] = 0ull;
    }
    __syncthreads();

    int p = pblk * 256 + tid;
    bool valid = (p < P);
    float px1, py1, px2, py2, areaB;
    if (valid) {
        float4 pr = ((const float4*)priors)[p];
        px1 = pr.x - pr.z * 0.5f; py1 = pr.y - pr.w * 0.5f;
        px2 = pr.x + pr.z * 0.5f; py2 = pr.y + pr.w * 0.5f;
        areaB = (px2 - px1) * (py2 - py1);
    } else {
        px1 = 3e9f; py1 = 3e9f; px2 = 3e9f; py2 = 3e9f; areaB = 0.f;
    }

    float best = -1.0f; int bestt = 0;
    int lane = tid & 31;
    for (int t = 0; t < T; t++) {
        float4 g = s_t[t];
        float ix = fminf(g.z, px2) - fmaxf(g.x, px1);
        float iy = fminf(g.w, py2) - fmaxf(g.y, py1);
        float inter = fmaxf(ix, 0.f) * fmaxf(iy, 0.f);
        float ov = __fdividef(inter, s_ar[t] + areaB - inter);
        if (ov > best) { best = ov; bestt = t; }        // strict > : first-t ties
        unsigned bits = valid ? __float_as_uint(ov) : 0u;
        unsigned wmax = __reduce_max_sync(0xFFFFFFFFu, bits);
        unsigned bal  = __ballot_sync(0xFFFFFFFFu, bits == wmax);
        if (lane == (__ffs(bal) - 1)) {
            unsigned long long enc = (((unsigned long long)wmax) << 32) |
                                     (unsigned long long)(0xFFFFFFFFu - (unsigned)p);
            if (enc > s_best[t]) atomicMax(&s_best[t], enc);
        }
    }
    if (valid) {
        g_bt_ov [(size_t)b * P + p] = best;
        g_bt_idx[(size_t)b * P + p] = bestt;
    }
    __syncthreads();
    if (tid < T && s_best[tid]) atomicMax(&g_best_enc[b * T + tid], s_best[tid]);
}

__device__ __forceinline__ void lse_body(const float* __restrict__ conf,
                                         int BP, int lseBlk) {
    int warp = lseBlk * 8 + (threadIdx.x >> 5);
    int lane = threadIdx.x & 31;
    int l = lane & 7;
    int row = warp * 4 + (lane >> 3);
    if (row >= BP) return;

    const float* base = conf + (size_t)row * 81 + l;
    float v0 = base[0];                    // lane l==0 holds the background logit
    float s = __expf(v0);
    #pragma unroll
    for (int k = 1; k < 10; k++) s += __expf(base[8 * k]);
    if (l == 0) s += __expf(base[80]);

    s += __shfl_xor_sync(0xFFFFFFFFu, s, 4);
    s += __shfl_xor_sync(0xFFFFFFFFu, s, 2);
    s += __shfl_xor_sync(0xFFFFFFFFu, s, 1);
    float lse = __logf(s);
    if (l == 0) g_lsebg[row] = make_float2(lse, v0);
}

__global__ void k_fused(const float* __restrict__ priors,
                        const float* __restrict__ tboxes,
                        const float* __restrict__ conf,
                        int P, int T, int BP, int matchBlocks, int mbx) {
    if ((int)blockIdx.x < matchBlocks) {
        int mb = blockIdx.x;
        match_body(priors, tboxes, P, T, mb / mbx, mb % mbx);
    } else {
        lse_body(conf, BP, blockIdx.x - matchBlocks);
    }
}

// ---------------- shared epilogue helpers -----------------------------------
__device__ __forceinline__ float sl1(float d) {
    float a = fabsf(d);
    return (a < 1.0f) ? 0.5f * d * d : a - 0.5f;
}

__device__ __forceinline__ void pos_epilogue(int bp, int b, int p, int T, int ti, float ce,
                                             const float* __restrict__ loc,
                                             const float* __restrict__ priors,
                                             const float* __restrict__ tboxes) {
    atomicAdd(&g_lossc_part[bp & (NSTRIPE - 1)], (double)ce);
    float4 ld = ((const float4*)loc)[bp];
    float4 pr = ((const float4*)priors)[p];
    const float* tb = tboxes + ((size_t)b * T + ti) * 4;
    float gx = ((tb[0] + tb[2]) * 0.5f - pr.x) / (0.1f * pr.z);
    float gy = ((tb[1] + tb[3]) * 0.5f - pr.y) / (0.1f * pr.w);
    float gw = logf((tb[2] - tb[0]) / pr.z) / 0.2f;
    float gh = logf((tb[3] - tb[1]) / pr.w) / 0.2f;
    float ll = sl1(ld.x - gx) + sl1(ld.y - gy) + sl1(ld.z - gw) + sl1(ld.w - gh);
    atomicAdd(&g_lossl_part[bp & (NSTRIPE - 1)], (double)ll);
}

// ---------------- fused force + ce-epilogue + hard-negative select ----------
// One block per batch. mine[] lives in dynamic shared memory (P floats).
#define SEL_THREADS 512
extern __shared__ float s_mine[];

__global__ void k_postsel(const float* __restrict__ conf,
                          const float* __restrict__ loc,
                          const float* __restrict__ priors,
                          const float* __restrict__ tboxes,
                          const int*   __restrict__ tlabels,
                          int P, int C, int T) {
    int b = blockIdx.x;
    int tid = threadIdx.x;
    int lane = tid & 31;
    int iters = (P + SEL_THREADS - 1) / SEL_THREADS;   // uniform trip count

    __shared__ int      s_fp[TMAX];
    __shared__ unsigned s_cnt[256];
    __shared__ unsigned s_prefix;
    __shared__ int      s_k;
    __shared__ int      s_np;
    __shared__ double   s_sum[SEL_THREADS];

    // ---- phase 0: force-match best prior of each gt (last-t-wins) ----
    if (tid == 0) s_np = 0;
    if (tid < T) {
        unsigned long long e = g_best_enc[b * T + tid];
        s_fp[tid] = e ? (int)(0xFFFFFFFFu - (unsigned)(e & 0xFFFFFFFFull)) : 0;
    }
    __syncthreads();
    if (tid < T) {
        int p = s_fp[tid];
        bool last = true;                   // sequential .at[].set semantics: higher t wins
        for (int t2 = tid + 1; t2 < T; t2++) if (s_fp[t2] == p) { last = false; break; }
        if (last) {
            g_bt_ov [(size_t)b * P + p] = 2.0f;
            g_bt_idx[(size_t)b * P + p] = tid;
        }
    }
    __syncthreads();   // global writes visible block-wide after barrier

    // ---- phase 1: compute mine into smem, count positives, pos epilogue ----
    const float*  ovp = g_bt_ov + (size_t)b * P;
    const float2* lb  = g_lsebg + (size_t)b * P;
    int npos = 0;
    for (int i = tid; i < P; i += SEL_THREADS) {   // no warp collectives inside
        float ov = ovp[i];
        float2 lg = lb[i];
        float m;
        if (ov < 0.5f) {
            m = lg.x - lg.y;                // ce vs background, candidate negative
        } else {
            m = 0.f;
            npos++;
            int bp = b * P + i;
            int ti = g_bt_idx[bp];
            int lab = tlabels[b * T + ti];
            float tgt = conf[(size_t)bp * C + (lab + 1)];
            pos_epilogue(bp, b, i, T, ti, lg.x - tgt, loc, priors, tboxes);
        }
        s_mine[i] = m;
    }
    #pragma unroll
    for (int o = 16; o > 0; o >>= 1) npos += __shfl_xor_sync(0xFFFFFFFFu, npos, o);
    if (lane == 0 && npos) atomicAdd(&s_np, npos);
    __syncthreads();

    int np = s_np;
    if (tid == 0) {
        g_num_pos[b] = np;
        int k = 3 * np;
        if (k > P - 1) k = P - 1;
        s_k = k;
        s_prefix = 0u;
    }
    __syncthreads();
    if (s_k <= 0) return;

    // ---- phase 2: 8-bit MSB radix select over smem mine ----
    // uniform iters loop: all threads reach every __match_any_sync
    for (int shift = 24; shift >= 0; shift -= 8) {
        if (tid < 256) s_cnt[tid] = 0;
        __syncthreads();
        unsigned pref = s_prefix;
        unsigned hm = (shift == 24) ? 0u : (0xFFFFFFFFu << (shift + 8));
        for (int it = 0; it < iters; it++) {
            int i = it * SEL_THREADS + tid;
            bool valid = (i < P);
            unsigned v = valid ? __float_as_uint(s_mine[i]) : 0u;
            bool ok = valid && ((v & hm) == (pref & hm));
            unsigned bin = ok ? ((v >> shift) & 255u) : 0xFFFFFFFFu;
            unsigned mm = __match_any_sync(0xFFFFFFFFu, bin);
            if (ok && lane == (__ffs(mm) - 1))
                atomicAdd(&s_cnt[bin], (unsigned)__popc(mm));
        }
        __syncthreads();
        if (tid == 0) {
            int k = s_k;
            int cum = 0;
            unsigned g = 0;
            for (int d = 255; d >= 0; d--) {
                int c = (int)s_cnt[d];
                if (cum + c >= k) { g = (unsigned)d; s_k = k - cum; break; }
                cum += c;
            }
            s_prefix = pref | (g << shift);
        }
        __syncthreads();
    }

    // ---- phase 3: sum of top-k (no collectives in loop) ----
    unsigned thr = s_prefix;
    double sum = 0.0;
    for (int i = tid; i < P; i += SEL_THREADS) {
        float f = s_mine[i];
        if (__float_as_uint(f) > thr) sum += (double)f;
    }
    if (tid == 0) sum += (double)s_k * (double)__uint_as_float(thr);
    s_sum[tid] = sum;
    __syncthreads();
    #pragma unroll
    for (int o = SEL_THREADS / 2; o > 0; o >>= 1) {
        if (tid < o) s_sum[tid] += s_sum[tid + o];
        __syncthreads();
    }
    if (tid == 0) atomicAdd(&g_lossc_part[b & (NSTRIPE - 1)], s_sum[0]);
}

// ---------------- generic fallback (any C): force + ce + select on gmem -----
__global__ void k_force(int B, int P, int T) {
    int b = blockIdx.x * blockDim.x + threadIdx.x;
    if (b >= B) return;
    for (int t = 0; t < T; t++) {
        unsigned long long enc = g_best_enc[b * T + t];
        unsigned p = enc ? (0xFFFFFFFFu - (unsigned)(enc & 0xFFFFFFFFull)) : 0u;
        g_bt_ov [(size_t)b * P + p] = 2.0f;
        g_bt_idx[(size_t)b * P + p] = t;
    }
}

__global__ void k_ce_gen(const float* __restrict__ conf,
                         const float* __restrict__ loc,
                         const float* __restrict__ priors,
                         const float* __restrict__ tboxes,
                         const int*   __restrict__ tlabels,
                         int B, int P, int C, int T) {
    int wg = (int)((blockIdx.x * (size_t)blockDim.x + threadIdx.x) >> 5);
    int lane = threadIdx.x & 31;
    if (wg >= B * P) return;
    int b = wg / P, p = wg % P;
    size_t base = ((size_t)b * P + p) * (size_t)C;

    float m = -INFINITY;
    for (int c = lane; c < C; c += 32) m = fmaxf(m, conf[base + c]);
    #pragma unroll
    for (int o = 16; o > 0; o >>= 1) m = fmaxf(m, __shfl_xor_sync(0xFFFFFFFFu, m, o));
    float s = 0.f;
    for (int c = lane; c < C; c += 32) s += __expf(conf[base + c] - m);
    #pragma unroll
    for (int o = 16; o > 0; o >>= 1) s += __shfl_xor_sync(0xFFFFFFFFu, s, o);
    float lse = m + __logf(s);

    if (lane == 0) {
        int bp = b * P + p;
        float ov = g_bt_ov[bp];
        int   ti = g_bt_idx[bp];
        int conf_t = (ov < 0.5f) ? 0 : (tlabels[b * T + ti] + 1);
        float ce = lse - conf[base + conf_t];
        bool pos = (conf_t > 0);
        g_mine[bp] = pos ? 0.0f : ce;
        if (pos) {
            atomicAdd(&g_num_pos[b], 1);
            pos_epilogue(bp, b, p, T, ti, ce, loc, priors, tboxes);
        }
    }
}

__global__ void k_select_gmem(int P) {
    int b = blockIdx.x;
    __shared__ unsigned s_cnt[256];
    __shared__ unsigned s_prefix;
    __shared__ int s_k;
    __shared__ double s_sum[SEL_THREADS];
    int tid = threadIdx.x;
    int lane = tid & 31;
    int iters = (P + SEL_THREADS - 1) / SEL_THREADS;

    if (tid == 0) {
        int np = g_num_pos[b];
        int k = 3 * np;
        if (k > P - 1) k = P - 1;
        s_k = k;
        s_prefix = 0u;
    }
    __syncthreads();
    if (s_k <= 0) return;

    const float* mine = g_mine + (size_t)b * P;
    for (int shift = 24; shift >= 0; shift -= 8) {
        if (tid < 256) s_cnt[tid] = 0;
        __syncthreads();
        unsigned pref = s_prefix;
        unsigned hm = (shift == 24) ? 0u : (0xFFFFFFFFu << (shift + 8));
        for (int it = 0; it < iters; it++) {
            int i = it * SEL_THREADS + tid;
            bool valid = (i < P);
            unsigned v = valid ? __float_as_uint(mine[i]) : 0u;
            bool ok = valid && ((v & hm) == (pref & hm));
            unsigned bin = ok ? ((v >> shift) & 255u) : 0xFFFFFFFFu;
            unsigned mm = __match_any_sync(0xFFFFFFFFu, bin);
            if (ok && lane == (__ffs(mm) - 1))
                atomicAdd(&s_cnt[bin], (unsigned)__popc(mm));
        }
        __syncthreads();
        if (tid == 0) {
            int k = s_k;
            int cum = 0;
            unsigned g = 0;
            for (int d = 255; d >= 0; d--) {
                int c = (int)s_cnt[d];
                if (cum + c >= k) { g = (unsigned)d; s_k = k - cum; break; }
                cum += c;
            }
            s_prefix = pref | (g << shift);
        }
        __syncthreads();
    }
    unsigned thr = s_prefix;
    double sum = 0.0;
    for (int i = tid; i < P; i += SEL_THREADS) {
        float f = mine[i];
        if (__float_as_uint(f) > thr) sum += (double)f;
    }
    if (tid == 0) sum += (double)s_k * (double)__uint_as_float(thr);
    s_sum[tid] = sum;
    __syncthreads();
    #pragma unroll
    for (int o = SEL_THREADS / 2; o > 0; o >>= 1) {
        if (tid < o) s_sum[tid] += s_sum[tid + o];
        __syncthreads();
    }
    if (tid == 0) atomicAdd(&g_lossc_part[b & (NSTRIPE - 1)], s_sum[0]);
}

// ---------------- finalize (parallel reduce of striped partials) ------------
__global__ void k_final(float* out, int B) {
    __shared__ double s_l[NSTRIPE];
    __shared__ double s_c[NSTRIPE];
    __shared__ int    s_n[64];
    int tid = threadIdx.x;
    s_l[tid] = g_lossl_part[tid];
    s_c[tid] = g_lossc_part[tid];
    s_n[tid & 63] = 0;
    __syncthreads();
    if (tid < B) s_n[tid] = g_num_pos[tid];
    __syncthreads();
    #pragma unroll
    for (int o = NSTRIPE / 2; o > 0; o >>= 1) {
        if (tid < o) { s_l[tid] += s_l[tid + o]; s_c[tid] += s_c[tid + o]; }
        if (o <= 32 && tid < o) s_n[tid] += s_n[tid + o];
        __syncthreads();
    }
    if (tid == 0) {
        int n = s_n[0];
        double nn = (n < 1) ? 1.0 : (double)n;
        out[0] = (float)(s_l[0] / nn);
        out[1] = (float)(s_c[0] / nn);
    }
}

// ---------------- launch ----------------------------------------------------
extern "C" void kernel_launch(void* const* d_in, const int* in_sizes, int n_in,
                              void* d_out, int out_size) {
    const float* loc     = (const float*)d_in[0];
    const float* conf    = (const float*)d_in[1];
    const float* priors  = (const float*)d_in[2];
    const float* tboxes  = (const float*)d_in[3];
    const int*   tlabels = (const int*)  d_in[4];
    float* out = (float*)d_out;

    int P  = in_sizes[2] / 4;
    int B  = in_sizes[0] / (4 * P);
    int T  = in_sizes[4] / B;
    int C  = (int)((long long)in_sizes[1] / ((long long)B * P));
    int BP = B * P;

    // 1. init scratch accumulators
    {
        int n = B * T;
        if (n < NSTRIPE) n = NSTRIPE;
        k_init<<<(n + 255) / 256, 256>>>(B, T);
    }
    size_t smemBytes = (size_t)P * sizeof(float);
    bool fast = (C == 81) && (smemBytes <= 160 * 1024) && (T <= TMAX);
    int mbx = (P + 255) / 256;
    int matchBlocks = mbx * B;
    if (fast) {
        // idempotent, deterministic, capture-safe (host-side attribute set)
        cudaFuncSetAttribute(k_postsel,
                             cudaFuncAttributeMaxDynamicSharedMemorySize,
                             (int)(160 * 1024));
        // 2. fused matching + logsumexp (independent work, co-resident overlap)
        long long warps = ((long long)BP + 3) / 4;
        long long lseBlocks = (warps + 7) / 8;         // 8 warps / block
        k_fused<<<(unsigned)(matchBlocks + lseBlocks), 256>>>(
            priors, tboxes, conf, P, T, BP, matchBlocks, mbx);
        // 3. force + ce epilogue + hard-negative select (smem-resident mine)
        k_postsel<<<B, SEL_THREADS, smemBytes>>>(conf, loc, priors, tboxes,
                                                 tlabels, P, C, T);
    } else {
        k_fused<<<dim3(matchBlocks), 256>>>(priors, tboxes, conf, P, T, BP,
                                            matchBlocks, mbx);
        k_force<<<(B + 63) / 64, 64>>>(B, P, T);
        long long blocks = ((long long)BP + 7) / 8;
        k_ce_gen<<<(unsigned)blocks, 256>>>(conf, loc, priors, tboxes, tlabels,
                                            B, P, C, T);
        k_select_gmem<<<B, SEL_THREADS>>>(P);
    }
    // 4. finalize
    k_final<<<1, NSTRIPE>>>(out, B);
}

// round 16
// speedup vs baseline: 1.2721x; 1.2721x over previous
#include <cuda_runtime.h>
#include <math.h>
#include <stdint.h>

// Problem-size maxima (fixed benchmark shape B=64, P=24564, C=81, T=50)
#define BMAX 64
#define PMAX 24564
#define TMAX 50
#define NSTRIPE 512
#define SEL_THREADS 512

// ---------------- scratch (__device__ globals; no allocation allowed) -------
// All state is returned to ZERO by k_selectfin's last block each run, so no
// init kernel is needed (device globals start zeroed at module load).
__device__ float               g_bt_ov [BMAX * PMAX];   // best truth overlap per prior
__device__ int                 g_bt_idx[BMAX * PMAX];   // best truth index per prior
__device__ float               g_mine  [BMAX * PMAX];   // loss_mine
__device__ float2              g_lsebg [BMAX * PMAX];   // {logsumexp, background logit}
__device__ unsigned long long  g_best_enc[BMAX * TMAX]; // per-gt best prior (encoded)
__device__ int                 g_num_pos[BMAX];
__device__ double              g_lossl_part[NSTRIPE];   // striped accumulators
__device__ double              g_lossc_part[NSTRIPE];
__device__ int                 g_ticket;

// ---------------- fused matching + streaming logsumexp (interleaved) --------
__device__ __forceinline__ void match_body(const float* __restrict__ priors,
                                           const float* __restrict__ tboxes,
                                           int P, int T, int b, int pblk) {
    __shared__ float4 s_t[TMAX];
    __shared__ float  s_ar[TMAX];
    __shared__ unsigned long long s_best[TMAX];
    int tid = threadIdx.x;
    if (tid < T) {
        const float* tb = tboxes + ((size_t)b * T + tid) * 4;
        float x1 = tb[0], y1 = tb[1], x2 = tb[2], y2 = tb[3];
        s_t[tid] = make_float4(x1, y1, x2, y2);
        s_ar[tid] = (x2 - x1) * (y2 - y1);
        s_best[tid] = 0ull;
    }
    __syncthreads();

    int p = pblk * 256 + tid;
    bool valid = (p < P);
    float px1, py1, px2, py2, areaB;
    if (valid) {
        float4 pr = ((const float4*)priors)[p];
        px1 = pr.x - pr.z * 0.5f; py1 = pr.y - pr.w * 0.5f;
        px2 = pr.x + pr.z * 0.5f; py2 = pr.y + pr.w * 0.5f;
        areaB = (px2 - px1) * (py2 - py1);
    } else {
        px1 = 3e9f; py1 = 3e9f; px2 = 3e9f; py2 = 3e9f; areaB = 0.f;
    }

    float best = -1.0f; int bestt = 0;
    int lane = tid & 31;
    for (int t = 0; t < T; t++) {
        float4 g = s_t[t];
        float ix = fminf(g.z, px2) - fmaxf(g.x, px1);
        float iy = fminf(g.w, py2) - fmaxf(g.y, py1);
        float inter = fmaxf(ix, 0.f) * fmaxf(iy, 0.f);
        float ov = __fdividef(inter, s_ar[t] + areaB - inter);
        if (ov > best) { best = ov; bestt = t; }        // strict > : first-t ties
        unsigned bits = valid ? __float_as_uint(ov) : 0u;
        unsigned wmax = __reduce_max_sync(0xFFFFFFFFu, bits);
        unsigned bal  = __ballot_sync(0xFFFFFFFFu, bits == wmax);
        if (lane == (__ffs(bal) - 1)) {
            unsigned long long enc = (((unsigned long long)wmax) << 32) |
                                     (unsigned long long)(0xFFFFFFFFu - (unsigned)p);
            if (enc > s_best[t]) atomicMax(&s_best[t], enc);
        }
    }
    if (valid) {
        g_bt_ov [(size_t)b * P + p] = best;
        g_bt_idx[(size_t)b * P + p] = bestt;
    }
    __syncthreads();
    if (tid < T && s_best[tid]) atomicMax(&g_best_enc[b * T + tid], s_best[tid]);
}

__device__ __forceinline__ void lse_body(const float* __restrict__ conf,
                                         int BP, int lseBlk) {
    int warp = lseBlk * 8 + (threadIdx.x >> 5);
    int lane = threadIdx.x & 31;
    int l = lane & 7;
    int row = warp * 4 + (lane >> 3);
    if (row >= BP) return;

    const float* base = conf + (size_t)row * 81 + l;
    float v0 = base[0];                    // lane l==0 holds the background logit
    float s = __expf(v0);
    #pragma unroll
    for (int k = 1; k < 10; k++) s += __expf(base[8 * k]);
    if (l == 0) s += __expf(base[80]);

    s += __shfl_xor_sync(0xFFFFFFFFu, s, 4);
    s += __shfl_xor_sync(0xFFFFFFFFu, s, 2);
    s += __shfl_xor_sync(0xFFFFFFFFu, s, 1);
    float lse = __logf(s);
    if (l == 0) g_lsebg[row] = make_float2(lse, v0);
}

// 1-in-stride blocks do matching; the rest do lse. Interleaving keeps both
// workloads co-resident in every wave so the ALU-bound match hides under the
// DRAM-bound lse.
__global__ void k_fused(const float* __restrict__ priors,
                        const float* __restrict__ tboxes,
                        const float* __restrict__ conf,
                        int P, int T, int BP, int mbx, int stride) {
    int bid = blockIdx.x;
    if (stride <= 1) {
        match_body(priors, tboxes, P, T, bid / mbx, bid % mbx);
        return;
    }
    if (bid % stride == 0) {
        int mb = bid / stride;
        match_body(priors, tboxes, P, T, mb / mbx, mb % mbx);
    } else {
        int lb = bid - bid / stride - 1;
        lse_body(conf, BP, lb);
    }
}

// ---------------- shared epilogue helpers -----------------------------------
__device__ __forceinline__ float sl1(float d) {
    float a = fabsf(d);
    return (a < 1.0f) ? 0.5f * d * d : a - 0.5f;
}

__device__ __forceinline__ void pos_epilogue(int bp, int b, int p, int T, int ti, float ce,
                                             const float* __restrict__ loc,
                                             const float* __restrict__ priors,
                                             const float* __restrict__ tboxes) {
    atomicAdd(&g_lossc_part[bp & (NSTRIPE - 1)], (double)ce);
    float4 ld = ((const float4*)loc)[bp];
    float4 pr = ((const float4*)priors)[p];
    const float* tb = tboxes + ((size_t)b * T + ti) * 4;
    float gx = ((tb[0] + tb[2]) * 0.5f - pr.x) / (0.1f * pr.z);
    float gy = ((tb[1] + tb[3]) * 0.5f - pr.y) / (0.1f * pr.w);
    float gw = logf((tb[2] - tb[0]) / pr.z) / 0.2f;
    float gh = logf((tb[3] - tb[1]) / pr.w) / 0.2f;
    float ll = sl1(ld.x - gx) + sl1(ld.y - gy) + sl1(ld.z - gw) + sl1(ld.w - gh);
    atomicAdd(&g_lossl_part[bp & (NSTRIPE - 1)], (double)ll);
}

// ---------------- postforce: force-match + mine + positives (full grid) -----
// grid (ceil(P4/256), B). Each thread handles 4 priors with vector loads.
// Force-match is applied in-register from the smem-cached enc list.
__device__ __forceinline__ float pf_handle(int b, int P, int C, int T,
                                           int p, float ov, int tif,
                                           float lse, float bg, int& np,
                                           const float* __restrict__ conf,
                                           const float* __restrict__ loc,
                                           const float* __restrict__ priors,
                                           const float* __restrict__ tboxes,
                                           const int*   __restrict__ tlabels) {
    if (ov < 0.5f) return lse - bg;        // background: ce vs class 0
    np++;
    int bp = b * P + p;
    int ti = (tif >= 0) ? tif : g_bt_idx[bp];   // lazy gather, rare path
    int lab = tlabels[b * T + ti];
    float tgt = conf[(size_t)bp * C + lab + 1];
    pos_epilogue(bp, b, p, T, ti, lse - tgt, loc, priors, tboxes);
    return 0.f;
}

__global__ void k_postforce(const float* __restrict__ conf,
                            const float* __restrict__ loc,
                            const float* __restrict__ priors,
                            const float* __restrict__ tboxes,
                            const int*   __restrict__ tlabels,
                            int P, int C, int T) {
    int b = blockIdx.y;
    int tid = threadIdx.x;
    int lane = tid & 31;
    __shared__ int s_fp[TMAX];
    if (tid < T) {
        unsigned long long e = g_best_enc[b * T + tid];
        s_fp[tid] = e ? (int)(0xFFFFFFFFu - (unsigned)(e & 0xFFFFFFFFull)) : 0;
    }
    __syncthreads();

    int P4 = P >> 2;
    int i4 = blockIdx.x * blockDim.x + tid;
    bool valid = (i4 < P4);
    int np = 0;
    if (valid) {
        int i0 = i4 * 4;
        size_t base = (size_t)b * P + i0;
        float4 ov4  = *(const float4*)(g_bt_ov + base);
        const float* lgf = (const float*)g_lsebg;
        float4 lg01 = *(const float4*)(lgf + 2 * base);
        float4 lg23 = *(const float4*)(lgf + 2 * base + 4);
        float ov0 = ov4.x, ov1 = ov4.y, ov2 = ov4.z, ov3 = ov4.w;
        int t0 = -1, t1 = -1, t2 = -1, t3 = -1;
        for (int t = 0; t < T; t++) {      // last-t-wins, matches .at[].set order
            unsigned d = (unsigned)(s_fp[t] - i0);
            if (d < 4u) {
                if (d == 0)      { ov0 = 2.f; t0 = t; }
                else if (d == 1) { ov1 = 2.f; t1 = t; }
                else if (d == 2) { ov2 = 2.f; t2 = t; }
                else             { ov3 = 2.f; t3 = t; }
            }
        }
        float4 mine;
        mine.x = pf_handle(b, P, C, T, i0 + 0, ov0, t0, lg01.x, lg01.y, np,
                           conf, loc, priors, tboxes, tlabels);
        mine.y = pf_handle(b, P, C, T, i0 + 1, ov1, t1, lg01.z, lg01.w, np,
                           conf, loc, priors, tboxes, tlabels);
        mine.z = pf_handle(b, P, C, T, i0 + 2, ov2, t2, lg23.x, lg23.y, np,
                           conf, loc, priors, tboxes, tlabels);
        mine.w = pf_handle(b, P, C, T, i0 + 3, ov3, t3, lg23.z, lg23.w, np,
                           conf, loc, priors, tboxes, tlabels);
        *(float4*)(g_mine + base) = mine;
    }
    #pragma unroll
    for (int o = 16; o > 0; o >>= 1) np += __shfl_xor_sync(0xFFFFFFFFu, np, o);
    if (lane == 0 && np) atomicAdd(&g_num_pos[b], np);
}

// ---------------- select + finalize (+ state re-zero for next replay) -------
__global__ void k_selectfin(float* out, int P, int B, int T) {
    int b = blockIdx.x;
    int tid = threadIdx.x;
    int lane = tid & 31;
    int iters = (P + SEL_THREADS - 1) / SEL_THREADS;   // uniform trip count

    __shared__ unsigned s_cnt[256];
    __shared__ unsigned s_prefix;
    __shared__ int      s_k;
    __shared__ int      s_last;
    __shared__ double   s_sl[SEL_THREADS];
    __shared__ double   s_sc[SEL_THREADS];
    __shared__ int      s_n[SEL_THREADS];

    // re-zero this batch's enc slice for the next replay (read already done
    // by k_postforce in the previous kernel)
    if (tid < T) g_best_enc[b * T + tid] = 0ull;

    int np = g_num_pos[b];
    int k0 = 3 * np;
    if (k0 > P - 1) k0 = P - 1;
    if (tid == 0) { s_k = k0; s_prefix = 0u; }
    __syncthreads();

    const float* mine = g_mine + (size_t)b * P;
    if (k0 > 0) {
        // 8-bit MSB radix select (uniform loops around warp collectives)
        for (int shift = 24; shift >= 0; shift -= 8) {
            if (tid < 256) s_cnt[tid] = 0;
            __syncthreads();
            unsigned pref = s_prefix;
            unsigned hm = (shift == 24) ? 0u : (0xFFFFFFFFu << (shift + 8));
            for (int it = 0; it < iters; it++) {
                int i = it * SEL_THREADS + tid;
                bool valid = (i < P);
                unsigned v = valid ? __float_as_uint(mine[i]) : 0u;
                bool ok = valid && ((v & hm) == (pref & hm));
                unsigned bin = ok ? ((v >> shift) & 255u) : 0xFFFFFFFFu;
                unsigned mm = __match_any_sync(0xFFFFFFFFu, bin);
                if (ok && lane == (__ffs(mm) - 1))
                    atomicAdd(&s_cnt[bin], (unsigned)__popc(mm));
            }
            __syncthreads();
            if (tid == 0) {
                int k = s_k;
                int cum = 0;
                unsigned g = 0;
                for (int d = 255; d >= 0; d--) {
                    int c = (int)s_cnt[d];
                    if (cum + c >= k) { g = (unsigned)d; s_k = k - cum; break; }
                    cum += c;
                }
                s_prefix = pref | (g << shift);
            }
            __syncthreads();
        }
        // sum of top-k
        unsigned thr = s_prefix;
        double sum = 0.0;
        for (int i = tid; i < P; i += SEL_THREADS) {
            float f = mine[i];
            if (__float_as_uint(f) > thr) sum += (double)f;
        }
        if (tid == 0) sum += (double)s_k * (double)__uint_as_float(thr);
        s_sl[tid] = sum;
        __syncthreads();
        #pragma unroll
        for (int o = SEL_THREADS / 2; o > 0; o >>= 1) {
            if (tid < o) s_sl[tid] += s_sl[tid + o];
            __syncthreads();
        }
        if (tid == 0) atomicAdd(&g_lossc_part[b & (NSTRIPE - 1)], s_sl[0]);
    }

    // ---- ticket: last-arriving block finalizes and re-zeros state ----
    __threadfence();
    if (tid == 0) {
        int t = atomicAdd(&g_ticket, 1);
        s_last = (t == B - 1) ? 1 : 0;
    }
    __syncthreads();
    if (!s_last) return;
    __threadfence();                       // acquire: see all blocks' atomics

    double l = g_lossl_part[tid];
    double c = g_lossc_part[tid];
    int n = (tid < B) ? g_num_pos[tid] : 0;
    // re-zero for the next replay
    g_lossl_part[tid] = 0.0;
    g_lossc_part[tid] = 0.0;
    if (tid < B) g_num_pos[tid] = 0;
    if (tid == 0) g_ticket = 0;

    s_sl[tid] = l; s_sc[tid] = c; s_n[tid] = n;
    __syncthreads();
    #pragma unroll
    for (int o = SEL_THREADS / 2; o > 0; o >>= 1) {
        if (tid < o) {
            s_sl[tid] += s_sl[tid + o];
            s_sc[tid] += s_sc[tid + o];
            s_n[tid]  += s_n[tid + o];
        }
        __syncthreads();
    }
    if (tid == 0) {
        int nn = s_n[0];
        double nd = (nn < 1) ? 1.0 : (double)nn;
        out[0] = (float)(s_sl[0] / nd);
        out[1] = (float)(s_sc[0] / nd);
    }
}

// ---------------- generic fallback (any C) ----------------------------------
__global__ void k_init(int B, int T) {
    int i = blockIdx.x * blockDim.x + threadIdx.x;
    if (i < NSTRIPE) { g_lossl_part[i] = 0.0; g_lossc_part[i] = 0.0; }
    if (i < B) g_num_pos[i] = 0;
    if (i < B * T) g_best_enc[i] = 0ull;
    if (i == 0) g_ticket = 0;
}

__global__ void k_force(int B, int P, int T) {
    int b = blockIdx.x * blockDim.x + threadIdx.x;
    if (b >= B) return;
    for (int t = 0; t < T; t++) {
        unsigned long long enc = g_best_enc[b * T + t];
        unsigned p = enc ? (0xFFFFFFFFu - (unsigned)(enc & 0xFFFFFFFFull)) : 0u;
        g_bt_ov [(size_t)b * P + p] = 2.0f;
        g_bt_idx[(size_t)b * P + p] = t;
    }
}

__global__ void k_ce_gen(const float* __restrict__ conf,
                         const float* __restrict__ loc,
                         const float* __restrict__ priors,
                         const float* __restrict__ tboxes,
                         const int*   __restrict__ tlabels,
                         int B, int P, int C, int T) {
    int wg = (int)((blockIdx.x * (size_t)blockDim.x + threadIdx.x) >> 5);
    int lane = threadIdx.x & 31;
    if (wg >= B * P) return;
    int b = wg / P, p = wg % P;
    size_t base = ((size_t)b * P + p) * (size_t)C;

    float m = -INFINITY;
    for (int c = lane; c < C; c += 32) m = fmaxf(m, conf[base + c]);
    #pragma unroll
    for (int o = 16; o > 0; o >>= 1) m = fmaxf(m, __shfl_xor_sync(0xFFFFFFFFu, m, o));
    float s = 0.f;
    for (int c = lane; c < C; c += 32) s += __expf(conf[base + c] - m);
    #pragma unroll
    for (int o = 16; o > 0; o >>= 1) s += __shfl_xor_sync(0xFFFFFFFFu, s, o);
    float lse = m + __logf(s);

    if (lane == 0) {
        int bp = b * P + p;
        float ov = g_bt_ov[bp];
        int   ti = g_bt_idx[bp];
        int conf_t = (ov < 0.5f) ? 0 : (tlabels[b * T + ti] + 1);
        float ce = lse - conf[base + conf_t];
        bool pos = (conf_t > 0);
        g_mine[bp] = pos ? 0.0f : ce;
        if (pos) {
            atomicAdd(&g_num_pos[b], 1);
            pos_epilogue(bp, b, p, T, ti, ce, loc, priors, tboxes);
        }
    }
}

__global__ void k_final(float* out, int B) {
    __shared__ double s_l[NSTRIPE];
    __shared__ double s_c[NSTRIPE];
    __shared__ int    s_n2[NSTRIPE];
    int tid = threadIdx.x;
    s_l[tid] = g_lossl_part[tid];
    s_c[tid] = g_lossc_part[tid];
    s_n2[tid] = (tid < B) ? g_num_pos[tid] : 0;
    __syncthreads();
    #pragma unroll
    for (int o = NSTRIPE / 2; o > 0; o >>= 1) {
        if (tid < o) { s_l[tid] += s_l[tid + o]; s_c[tid] += s_c[tid + o];
                       s_n2[tid] += s_n2[tid + o]; }
        __syncthreads();
    }
    if (tid == 0) {
        int n = s_n2[0];
        double nn = (n < 1) ? 1.0 : (double)n;
        out[0] = (float)(s_l[0] / nn);
        out[1] = (float)(s_c[0] / nn);
    }
}

// ---------------- launch ----------------------------------------------------
extern "C" void kernel_launch(void* const* d_in, const int* in_sizes, int n_in,
                              void* d_out, int out_size) {
    const float* loc     = (const float*)d_in[0];
    const float* conf    = (const float*)d_in[1];
    const float* priors  = (const float*)d_in[2];
    const float* tboxes  = (const float*)d_in[3];
    const int*   tlabels = (const int*)  d_in[4];
    float* out = (float*)d_out;

    int P  = in_sizes[2] / 4;
    int B  = in_sizes[0] / (4 * P);
    int T  = in_sizes[4] / B;
    int C  = (int)((long long)in_sizes[1] / ((long long)B * P));
    int BP = B * P;

    int mbx = (P + 255) / 256;
    int matchBlocks = mbx * B;
    bool fast = (C == 81) && ((P & 3) == 0) && (T <= TMAX) && (B <= BMAX);

    if (fast) {
        long long warps = ((long long)BP + 3) / 4;
        long long lseBlocks = (warps + 7) / 8;         // 8 warps / block
        int stride = (int)(lseBlocks / matchBlocks) + 2; // lse capacity >= lseBlocks
        long long grid = (long long)stride * matchBlocks;
        // 1. fused interleaved matching + logsumexp
        k_fused<<<(unsigned)grid, 256>>>(priors, tboxes, conf, P, T, BP, mbx, stride);
        // 2. force-match (in-register) + mine + positive epilogue
        {
            int P4 = P >> 2;
            dim3 g((P4 + 255) / 256, B);
            k_postforce<<<g, 256>>>(conf, loc, priors, tboxes, tlabels, P, C, T);
        }
        // 3. hard-negative select + finalize + state re-zero
        k_selectfin<<<B, SEL_THREADS>>>(out, P, B, T);
    } else {
        int n = B * T;
        if (n < NSTRIPE) n = NSTRIPE;
        k_init<<<(n + 255) / 256, 256>>>(B, T);
        k_fused<<<matchBlocks, 256>>>(priors, tboxes, conf, P, T, BP, mbx, 1);
        k_force<<<(B + 63) / 64, 64>>>(B, P, T);
        long long blocks = ((long long)BP + 7) / 8;
        k_ce_gen<<<(unsigned)blocks, 256>>>(conf, loc, priors, tboxes, tlabels,
                                            B, P, C, T);
        k_selectfin<<<B, SEL_THREADS>>>(out, P, B, T);
    }
}

// round 17
// speedup vs baseline: 1.4565x; 1.1450x over previous
#include <cuda_runtime.h>
#include <math.h>
#include <stdint.h>

// Problem-size maxima (fixed benchmark shape B=64, P=24564, C=81, T=50)
#define BMAX 64
#define PMAX 24564
#define TMAX 50
#define NSTRIPE 512
#define SEL_THREADS 512

// ---------------- scratch (__device__ globals; no allocation allowed) -------
// All persistent state is returned to ZERO by k_selectfin each run, so no
// init kernel is needed (device globals start zeroed at module load).
__device__ float               g_bt_ov [BMAX * PMAX];   // best truth overlap per prior
__device__ int                 g_bt_idx[BMAX * PMAX];   // best truth index per prior
__device__ float               g_mine  [BMAX * PMAX];   // loss_mine
__device__ float2              g_lsebg [BMAX * PMAX];   // {logsumexp, background logit}
__device__ unsigned long long  g_best_enc[BMAX * TMAX]; // per-gt best prior (encoded)
__device__ int                 g_num_pos[BMAX];
__device__ unsigned            g_hist[BMAX * 256];      // pass-1 radix histogram
__device__ double              g_lossl_part[NSTRIPE];   // striped accumulators
__device__ double              g_lossc_part[NSTRIPE];
__device__ int                 g_ticket;

// ---------------- fused matching + streaming logsumexp (interleaved) --------
__device__ __forceinline__ void match_body(const float* __restrict__ priors,
                                           const float* __restrict__ tboxes,
                                           int P, int T, int b, int pblk) {
    __shared__ float4 s_t[TMAX];
    __shared__ float  s_ar[TMAX];
    __shared__ unsigned long long s_best[TMAX];
    int tid = threadIdx.x;
    if (tid < T) {
        const float* tb = tboxes + ((size_t)b * T + tid) * 4;
        float x1 = tb[0], y1 = tb[1], x2 = tb[2], y2 = tb[3];
        s_t[tid] = make_float4(x1, y1, x2, y2);
        s_ar[tid] = (x2 - x1) * (y2 - y1);
        s_best[tid] = 0ull;
    }
    __syncthreads();

    int p = pblk * 256 + tid;
    bool valid = (p < P);
    float px1, py1, px2, py2, areaB;
    if (valid) {
        float4 pr = ((const float4*)priors)[p];
        px1 = pr.x - pr.z * 0.5f; py1 = pr.y - pr.w * 0.5f;
        px2 = pr.x + pr.z * 0.5f; py2 = pr.y + pr.w * 0.5f;
        areaB = (px2 - px1) * (py2 - py1);
    } else {
        // inter = 0, denom = areaA > 0  ->  ov = 0 exactly (no NaN)
        px1 = 3e9f; py1 = 3e9f; px2 = 3e9f; py2 = 3e9f; areaB = 0.f;
    }
    unsigned long long notp = (unsigned long long)(0xFFFFFFFFu - (unsigned)p);

    float best = -1.0f; int bestt = 0;
    #pragma unroll 10
    for (int t = 0; t < T; t++) {
        float4 g = s_t[t];
        float ix = fminf(g.z, px2) - fmaxf(g.x, px1);
        float iy = fminf(g.w, py2) - fmaxf(g.y, py1);
        float inter = fmaxf(ix, 0.f) * fmaxf(iy, 0.f);
        float ov = __fdividef(inter, s_ar[t] + areaB - inter);
        if (ov > best) { best = ov; bestt = t; }        // strict > : first-t ties
        unsigned bits = __float_as_uint(ov);            // invalid lanes: ov==0
        unsigned wmax = __reduce_max_sync(0xFFFFFFFFu, bits);
        if (bits == wmax) {                             // all tied lanes; max picks
            unsigned long long enc = (((unsigned long long)wmax) << 32) | notp;
            atomicMax(&s_best[t], enc);                 //   smallest p (largest ~p)
        }
    }
    if (valid) {
        g_bt_ov [(size_t)b * P + p] = best;
        g_bt_idx[(size_t)b * P + p] = bestt;
    }
    __syncthreads();
    if (tid < T && s_best[tid]) atomicMax(&g_best_enc[b * T + tid], s_best[tid]);
}

__device__ __forceinline__ void lse_body(const float* __restrict__ conf,
                                         int BP, int lseBlk) {
    int warp = lseBlk * 8 + (threadIdx.x >> 5);
    int lane = threadIdx.x & 31;
    int l = lane & 7;
    int row = warp * 4 + (lane >> 3);
    if (row >= BP) return;

    const float* base = conf + (size_t)row * 81 + l;
    float v0 = base[0];                    // lane l==0 holds the background logit
    float s = __expf(v0);
    #pragma unroll
    for (int k = 1; k < 10; k++) s += __expf(base[8 * k]);
    if (l == 0) s += __expf(base[80]);

    s += __shfl_xor_sync(0xFFFFFFFFu, s, 4);
    s += __shfl_xor_sync(0xFFFFFFFFu, s, 2);
    s += __shfl_xor_sync(0xFFFFFFFFu, s, 1);
    float lse = __logf(s);
    if (l == 0) g_lsebg[row] = make_float2(lse, v0);
}

// 1-in-stride blocks do matching; the rest do lse. Interleaving keeps both
// workloads co-resident in every wave so the ALU-bound match hides under the
// DRAM-bound lse.
__global__ void k_fused(const float* __restrict__ priors,
                        const float* __restrict__ tboxes,
                        const float* __restrict__ conf,
                        int P, int T, int BP, int mbx, int stride) {
    int bid = blockIdx.x;
    if (stride <= 1) {
        match_body(priors, tboxes, P, T, bid / mbx, bid % mbx);
        return;
    }
    if (bid % stride == 0) {
        int mb = bid / stride;
        match_body(priors, tboxes, P, T, mb / mbx, mb % mbx);
    } else {
        int lb = bid - bid / stride - 1;
        lse_body(conf, BP, lb);
    }
}

// ---------------- shared epilogue helpers -----------------------------------
__device__ __forceinline__ float sl1(float d) {
    float a = fabsf(d);
    return (a < 1.0f) ? 0.5f * d * d : a - 0.5f;
}

__device__ __forceinline__ void pos_epilogue(int bp, int b, int p, int T, int ti, float ce,
                                             const float* __restrict__ loc,
                                             const float* __restrict__ priors,
                                             const float* __restrict__ tboxes) {
    atomicAdd(&g_lossc_part[bp & (NSTRIPE - 1)], (double)ce);
    float4 ld = ((const float4*)loc)[bp];
    float4 pr = ((const float4*)priors)[p];
    const float* tb = tboxes + ((size_t)b * T + ti) * 4;
    float gx = ((tb[0] + tb[2]) * 0.5f - pr.x) / (0.1f * pr.z);
    float gy = ((tb[1] + tb[3]) * 0.5f - pr.y) / (0.1f * pr.w);
    float gw = logf((tb[2] - tb[0]) / pr.z) / 0.2f;
    float gh = logf((tb[3] - tb[1]) / pr.w) / 0.2f;
    float ll = sl1(ld.x - gx) + sl1(ld.y - gy) + sl1(ld.z - gw) + sl1(ld.w - gh);
    atomicAdd(&g_lossl_part[bp & (NSTRIPE - 1)], (double)ll);
}

// ---------------- postforce: force-match + mine + positives + hist ----------
// grid (ceil(P4/256), B). Each thread handles 4 priors with vector loads.
// Also builds the radix pass-1 (top byte) histogram of mine per batch.
__device__ __forceinline__ float pf_handle(int b, int P, int C, int T,
                                           int p, float ov, int tif,
                                           float lse, float bg, int& np,
                                           const float* __restrict__ conf,
                                           const float* __restrict__ loc,
                                           const float* __restrict__ priors,
                                           const float* __restrict__ tboxes,
                                           const int*   __restrict__ tlabels) {
    if (ov < 0.5f) return lse - bg;        // background: ce vs class 0
    np++;
    int bp = b * P + p;
    int ti = (tif >= 0) ? tif : g_bt_idx[bp];   // lazy gather, rare path
    int lab = tlabels[b * T + ti];
    float tgt = conf[(size_t)bp * C + lab + 1];
    pos_epilogue(bp, b, p, T, ti, lse - tgt, loc, priors, tboxes);
    return 0.f;
}

__global__ void k_postforce(const float* __restrict__ conf,
                            const float* __restrict__ loc,
                            const float* __restrict__ priors,
                            const float* __restrict__ tboxes,
                            const int*   __restrict__ tlabels,
                            int P, int C, int T) {
    int b = blockIdx.y;
    int tid = threadIdx.x;
    int lane = tid & 31;
    __shared__ int s_fp[TMAX];
    __shared__ unsigned s_h[256];
    s_h[tid] = 0u;
    if (tid < T) {
        unsigned long long e = g_best_enc[b * T + tid];
        s_fp[tid] = e ? (int)(0xFFFFFFFFu - (unsigned)(e & 0xFFFFFFFFull)) : 0;
    }
    __syncthreads();

    int P4 = P >> 2;
    int i4 = blockIdx.x * blockDim.x + tid;
    bool valid = (i4 < P4);
    int np = 0;
    if (valid) {
        int i0 = i4 * 4;
        size_t base = (size_t)b * P + i0;
        float4 ov4  = *(const float4*)(g_bt_ov + base);
        const float* lgf = (const float*)g_lsebg;
        float4 lg01 = *(const float4*)(lgf + 2 * base);
        float4 lg23 = *(const float4*)(lgf + 2 * base + 4);
        float ov0 = ov4.x, ov1 = ov4.y, ov2 = ov4.z, ov3 = ov4.w;
        int t0 = -1, t1 = -1, t2 = -1, t3 = -1;
        for (int t = 0; t < T; t++) {      // last-t-wins, matches .at[].set order
            unsigned d = (unsigned)(s_fp[t] - i0);
            if (d < 4u) {
                if (d == 0)      { ov0 = 2.f; t0 = t; }
                else if (d == 1) { ov1 = 2.f; t1 = t; }
                else if (d == 2) { ov2 = 2.f; t2 = t; }
                else             { ov3 = 2.f; t3 = t; }
            }
        }
        float4 mine;
        mine.x = pf_handle(b, P, C, T, i0 + 0, ov0, t0, lg01.x, lg01.y, np,
                           conf, loc, priors, tboxes, tlabels);
        mine.y = pf_handle(b, P, C, T, i0 + 1, ov1, t1, lg01.z, lg01.w, np,
                           conf, loc, priors, tboxes, tlabels);
        mine.z = pf_handle(b, P, C, T, i0 + 2, ov2, t2, lg23.x, lg23.y, np,
                           conf, loc, priors, tboxes, tlabels);
        mine.w = pf_handle(b, P, C, T, i0 + 3, ov3, t3, lg23.z, lg23.w, np,
                           conf, loc, priors, tboxes, tlabels);
        *(float4*)(g_mine + base) = mine;
        atomicAdd(&s_h[__float_as_uint(mine.x) >> 24], 1u);
        atomicAdd(&s_h[__float_as_uint(mine.y) >> 24], 1u);
        atomicAdd(&s_h[__float_as_uint(mine.z) >> 24], 1u);
        atomicAdd(&s_h[__float_as_uint(mine.w) >> 24], 1u);
    }
    #pragma unroll
    for (int o = 16; o > 0; o >>= 1) np += __shfl_xor_sync(0xFFFFFFFFu, np, o);
    if (lane == 0 && np) atomicAdd(&g_num_pos[b], np);
    __syncthreads();
    if (s_h[tid]) atomicAdd(&g_hist[b * 256 + tid], s_h[tid]);
}

// ---------------- select + finalize (+ state re-zero for next replay) -------
__global__ void k_selectfin(float* out, int P, int B, int T, int useHist) {
    int b = blockIdx.x;
    int tid = threadIdx.x;
    int lane = tid & 31;
    int iters = (P + SEL_THREADS - 1) / SEL_THREADS;   // uniform trip count

    __shared__ unsigned s_cnt[256];
    __shared__ unsigned s_prefix;
    __shared__ int      s_k;
    __shared__ int      s_last;
    __shared__ double   s_sl[SEL_THREADS];
    __shared__ double   s_sc[SEL_THREADS];
    __shared__ int      s_n[SEL_THREADS];

    // re-zero this batch's enc slice + histogram for the next replay
    if (tid < T) g_best_enc[b * T + tid] = 0ull;
    unsigned h0 = 0u;
    if (tid < 256) {
        h0 = g_hist[b * 256 + tid];
        g_hist[b * 256 + tid] = 0u;
    }

    int np = g_num_pos[b];
    int k0 = 3 * np;
    if (k0 > P - 1) k0 = P - 1;
    if (tid == 0) { s_k = k0; s_prefix = 0u; }
    if (tid < 256) s_cnt[tid] = h0;
    __syncthreads();

    const float* mine = g_mine + (size_t)b * P;
    if (k0 > 0) {
        int shift0;
        if (useHist) {
            // pass 1 comes from the precomputed histogram
            if (tid == 0) {
                int k = s_k;
                int cum = 0;
                unsigned g = 0;
                for (int d = 255; d >= 0; d--) {
                    int c = (int)s_cnt[d];
                    if (cum + c >= k) { g = (unsigned)d; s_k = k - cum; break; }
                    cum += c;
                }
                s_prefix = g << 24;
            }
            __syncthreads();
            shift0 = 16;
        } else {
            shift0 = 24;
        }
        // remaining radix passes (uniform loops around warp collectives)
        for (int shift = shift0; shift >= 0; shift -= 8) {
            if (tid < 256) s_cnt[tid] = 0;
            __syncthreads();
            unsigned pref = s_prefix;
            unsigned hm = (shift == 24) ? 0u : (0xFFFFFFFFu << (shift + 8));
            for (int it = 0; it < iters; it++) {
                int i = it * SEL_THREADS + tid;
                bool valid = (i < P);
                unsigned v = valid ? __float_as_uint(mine[i]) : 0u;
                bool ok = valid && ((v & hm) == (pref & hm));
                unsigned bin = ok ? ((v >> shift) & 255u) : 0xFFFFFFFFu;
                unsigned mm = __match_any_sync(0xFFFFFFFFu, bin);
                if (ok && lane == (__ffs(mm) - 1))
                    atomicAdd(&s_cnt[bin], (unsigned)__popc(mm));
            }
            __syncthreads();
            if (tid == 0) {
                int k = s_k;
                int cum = 0;
                unsigned g = 0;
                for (int d = 255; d >= 0; d--) {
                    int c = (int)s_cnt[d];
                    if (cum + c >= k) { g = (unsigned)d; s_k = k - cum; break; }
                    cum += c;
                }
                s_prefix = pref | (g << shift);
            }
            __syncthreads();
        }
        // sum of top-k
        unsigned thr = s_prefix;
        double sum = 0.0;
        for (int i = tid; i < P; i += SEL_THREADS) {
            float f = mine[i];
            if (__float_as_uint(f) > thr) sum += (double)f;
        }
        if (tid == 0) sum += (double)s_k * (double)__uint_as_float(thr);
        s_sl[tid] = sum;
        __syncthreads();
        #pragma unroll
        for (int o = SEL_THREADS / 2; o > 0; o >>= 1) {
            if (tid < o) s_sl[tid] += s_sl[tid + o];
            __syncthreads();
        }
        if (tid == 0) atomicAdd(&g_lossc_part[b & (NSTRIPE - 1)], s_sl[0]);
    }

    // ---- ticket: last-arriving block finalizes and re-zeros state ----
    __threadfence();
    if (tid == 0) {
        int t = atomicAdd(&g_ticket, 1);
        s_last = (t == B - 1) ? 1 : 0;
    }
    __syncthreads();
    if (!s_last) return;
    __threadfence();                       // acquire: see all blocks' atomics

    double l = g_lossl_part[tid];
    double c = g_lossc_part[tid];
    int n = (tid < B) ? g_num_pos[tid] : 0;
    // re-zero for the next replay
    g_lossl_part[tid] = 0.0;
    g_lossc_part[tid] = 0.0;
    if (tid < B) g_num_pos[tid] = 0;
    if (tid == 0) g_ticket = 0;

    s_sl[tid] = l; s_sc[tid] = c; s_n[tid] = n;
    __syncthreads();
    #pragma unroll
    for (int o = SEL_THREADS / 2; o > 0; o >>= 1) {
        if (tid < o) {
            s_sl[tid] += s_sl[tid + o];
            s_sc[tid] += s_sc[tid + o];
            s_n[tid]  += s_n[tid + o];
        }
        __syncthreads();
    }
    if (tid == 0) {
        int nn = s_n[0];
        double nd = (nn < 1) ? 1.0 : (double)nn;
        out[0] = (float)(s_sl[0] / nd);
        out[1] = (float)(s_sc[0] / nd);
    }
}

// ---------------- generic fallback (any C) ----------------------------------
__global__ void k_init(int B, int T) {
    int i = blockIdx.x * blockDim.x + threadIdx.x;
    if (i < NSTRIPE) { g_lossl_part[i] = 0.0; g_lossc_part[i] = 0.0; }
    if (i < B) g_num_pos[i] = 0;
    if (i < B * T) g_best_enc[i] = 0ull;
    if (i < BMAX * 256) g_hist[i] = 0u;
    if (i == 0) g_ticket = 0;
}

__global__ void k_force(int B, int P, int T) {
    int b = blockIdx.x * blockDim.x + threadIdx.x;
    if (b >= B) return;
    for (int t = 0; t < T; t++) {
        unsigned long long enc = g_best_enc[b * T + t];
        unsigned p = enc ? (0xFFFFFFFFu - (unsigned)(enc & 0xFFFFFFFFull)) : 0u;
        g_bt_ov [(size_t)b * P + p] = 2.0f;
        g_bt_idx[(size_t)b * P + p] = t;
    }
}

__global__ void k_ce_gen(const float* __restrict__ conf,
                         const float* __restrict__ loc,
                         const float* __restrict__ priors,
                         const float* __restrict__ tboxes,
                         const int*   __restrict__ tlabels,
                         int B, int P, int C, int T) {
    int wg = (int)((blockIdx.x * (size_t)blockDim.x + threadIdx.x) >> 5);
    int lane = threadIdx.x & 31;
    if (wg >= B * P) return;
    int b = wg / P, p = wg % P;
    size_t base = ((size_t)b * P + p) * (size_t)C;

    float m = -INFINITY;
    for (int c = lane; c < C; c += 32) m = fmaxf(m, conf[base + c]);
    #pragma unroll
    for (int o = 16; o > 0; o >>= 1) m = fmaxf(m, __shfl_xor_sync(0xFFFFFFFFu, m, o));
    float s = 0.f;
    for (int c = lane; c < C; c += 32) s += __expf(conf[base + c] - m);
    #pragma unroll
    for (int o = 16; o > 0; o >>= 1) s += __shfl_xor_sync(0xFFFFFFFFu, s, o);
    float lse = m + __logf(s);

    if (lane == 0) {
        int bp = b * P + p;
        float ov = g_bt_ov[bp];
        int   ti = g_bt_idx[bp];
        int conf_t = (ov < 0.5f) ? 0 : (tlabels[b * T + ti] + 1);
        float ce = lse - conf[base + conf_t];
        bool pos = (conf_t > 0);
        g_mine[bp] = pos ? 0.0f : ce;
        if (pos) {
            atomicAdd(&g_num_pos[b], 1);
            pos_epilogue(bp, b, p, T, ti, ce, loc, priors, tboxes);
        }
    }
}

// ---------------- launch ----------------------------------------------------
extern "C" void kernel_launch(void* const* d_in, const int* in_sizes, int n_in,
                              void* d_out, int out_size) {
    const float* loc     = (const float*)d_in[0];
    const float* conf    = (const float*)d_in[1];
    const float* priors  = (const float*)d_in[2];
    const float* tboxes  = (const float*)d_in[3];
    const int*   tlabels = (const int*)  d_in[4];
    float* out = (float*)d_out;

    int P  = in_sizes[2] / 4;
    int B  = in_sizes[0] / (4 * P);
    int T  = in_sizes[4] / B;
    int C  = (int)((long long)in_sizes[1] / ((long long)B * P));
    int BP = B * P;

    int mbx = (P + 255) / 256;
    int matchBlocks = mbx * B;
    bool fast = (C == 81) && ((P & 3) == 0) && (T <= TMAX) && (B <= BMAX);

    if (fast) {
        long long warps = ((long long)BP + 3) / 4;
        long long lseBlocks = (warps + 7) / 8;         // 8 warps / block
        int stride = (int)(lseBlocks / matchBlocks) + 2; // lse capacity >= lseBlocks
        long long grid = (long long)stride * matchBlocks;
        // 1. fused interleaved matching + logsumexp
        k_fused<<<(unsigned)grid, 256>>>(priors, tboxes, conf, P, T, BP, mbx, stride);
        // 2. force-match (in-register) + mine + positive epilogue + hist
        {
            int P4 = P >> 2;
            dim3 g((P4 + 255) / 256, B);
            k_postforce<<<g, 256>>>(conf, loc, priors, tboxes, tlabels, P, C, T);
        }
        // 3. hard-negative select (3 passes, hist pass precomputed) + finalize
        k_selectfin<<<B, SEL_THREADS>>>(out, P, B, T, 1);
    } else {
        int n = BMAX * 256;
        k_init<<<(n + 255) / 256, 256>>>(B, T);
        k_fused<<<matchBlocks, 256>>>(priors, tboxes, conf, P, T, BP, mbx, 1);
        k_force<<<(B + 63) / 64, 64>>>(B, P, T);
        long long blocks = ((long long)BP + 7) / 8;
        k_ce_gen<<<(unsigned)blocks, 256>>>(conf, loc, priors, tboxes, tlabels,
                                            B, P, C, T);
        k_selectfin<<<B, SEL_THREADS>>>(out, P, B, T, 0);
    }
}